// round 9
// baseline (speedup 1.0000x reference)
#include <cuda_runtime.h>
#include <math.h>
#include <stdint.h>

// Problem constants (fixed shapes)
constexpr int Bn   = 4;
constexpr int Ln   = 2048;
constexpr int Dn   = 512;
constexpr int BLn  = Bn * Ln;   // 8192
constexpr int KTOP = 4;         // int(log(64)) = 4

// Scratch (device globals — no runtime allocation)
__device__ float g_vproj[BLn * Dn];      // values @ wv
__device__ float g_abuf [BLn * Dn];      // permuted weighted-rolled transpose (rounded + K-permuted)
__device__ float g_wvT  [Dn * Dn];       // wv transposed, rounded + K-permuted
__device__ float g_woT  [Dn * Dn];       // wo transposed, rounded + K-permuted
__device__ float g_partial[Bn * 16 * Dn];
__device__ float g_u    [Bn * Dn];
__device__ float g_score[Bn * Ln];
__device__ float g_w    [Bn * KTOP];
__device__ int   g_shift[Bn * KTOP];

// ---------------------------------------------------------------------------
__device__ __forceinline__ float tf32r(float x) {
    uint32_t u;
    asm("cvt.rna.tf32.f32 %0, %1;" : "=r"(u) : "f"(x));
    return __uint_as_float(u);
}
// K-permutation within each 8-group: k<4 -> 2k, k>=4 -> 2(k-4)+1
__device__ __forceinline__ int kperm(int k) {
    int low = k & 7;
    return (k & ~7) | ((low < 4) ? (low << 1) : (((low - 4) << 1) | 1));
}

#define CP_ASYNC16(dst_u32, src_ptr) \
    asm volatile("cp.async.cg.shared.global [%0], [%1], 16;" :: "r"(dst_u32), "l"(src_ptr))
#define CP_COMMIT() asm volatile("cp.async.commit_group;")

// ---------------------------------------------------------------------------
// K1a: partial column sums of queries over 128-row chunks
__global__ void k_colsum_partial(const float* __restrict__ q) {
    int b = blockIdx.x >> 4, lc = blockIdx.x & 15, m = threadIdx.x;
    const float* p = q + ((size_t)(b * Ln + lc * 128)) * Dn + m;
    float acc = 0.f;
#pragma unroll 8
    for (int r = 0; r < 128; r++) acc += p[(size_t)r * Dn];
    g_partial[(size_t)blockIdx.x * Dn + m] = acc;
}

// K2: qmean reduce + qbar = qmean @ wq ; u = wk @ qbar   (one block per batch)
__global__ void k_project_u(const float* __restrict__ wq, const float* __restrict__ wk) {
    int b = blockIdx.x, tid = threadIdx.x;   // 512 threads
    __shared__ float sq[Dn];
    __shared__ float sqb[Dn];
    {
        float acc = 0.f;
#pragma unroll
        for (int lc = 0; lc < 16; lc++) acc += g_partial[(size_t)(b * 16 + lc) * Dn + tid];
        sq[tid] = acc * (1.0f / Ln);
    }
    __syncthreads();
    float acc = 0.f;
    for (int k2 = 0; k2 < Dn; k2++) acc += sq[k2] * wq[(size_t)k2 * Dn + tid];
    sqb[tid] = acc;
    __syncthreads();
    int lane = tid & 31, w = tid >> 5;       // 16 warps
    for (int d = w; d < Dn; d += 16) {
        const float4* row = (const float4*)(wk + (size_t)d * Dn);
        float s = 0.f;
#pragma unroll
        for (int i = 0; i < 4; i++) {
            int idx = lane + i * 32;
            float4 v = row[idx];
            s += v.x * sqb[idx * 4] + v.y * sqb[idx * 4 + 1] +
                 v.z * sqb[idx * 4 + 2] + v.w * sqb[idx * 4 + 3];
        }
        for (int off = 16; off; off >>= 1) s += __shfl_down_sync(0xffffffffu, s, off);
        if (lane == 0) g_u[b * Dn + d] = s;
    }
}

// K3: score[b,j] = (1/8) * <keys[b,j,:], u[b,:]> — one warp per row
__global__ void k_score(const float* __restrict__ keys) {
    int j = blockIdx.x * 8 + (threadIdx.x >> 5);
    int lane = threadIdx.x & 31;
    int b = j >> 11;
    const float4* kr = (const float4*)(keys + (size_t)j * Dn);
    const float4* ur = (const float4*)(g_u + (size_t)b * Dn);
    float s = 0.f;
#pragma unroll
    for (int i = 0; i < 4; i++) {
        float4 kv = kr[lane + i * 32];
        float4 uv = ur[lane + i * 32];
        s += kv.x * uv.x + kv.y * uv.y + kv.z * uv.z + kv.w * uv.w;
    }
    for (int off = 16; off; off >>= 1) s += __shfl_down_sync(0xffffffffu, s, off);
    if (lane == 0) g_score[j] = s * 0.125f;
}

// K4: top-4 (descending, ties -> lower index) + softmax. Register-resident.
__global__ void k_topk() {
    int b = blockIdx.x, tid = threadIdx.x;   // 256 threads, 8 warps
    int lane = tid & 31, w = tid >> 5;
    float v[8]; int vi[8];
#pragma unroll
    for (int i = 0; i < 8; i++) {
        int idx = tid + i * 256;
        v[i] = g_score[b * Ln + idx];
        vi[i] = idx;
    }
    __shared__ float wv_[8];
    __shared__ int   wi_[8];
    __shared__ float selv[KTOP];
    __shared__ int   seli[KTOP];
    if (tid < KTOP) seli[tid] = -1;
    __syncthreads();
    for (int r = 0; r < KTOP; r++) {
        float bv = -3.4e38f; int bi = 0x7fffffff;
#pragma unroll
        for (int i = 0; i < 8; i++) {
            bool dead = false;
#pragma unroll
            for (int p = 0; p < KTOP; p++) dead |= (p < r && vi[i] == seli[p]);
            float x = dead ? -3.4e38f : v[i];
            if (x > bv || (x == bv && vi[i] < bi)) { bv = x; bi = vi[i]; }
        }
#pragma unroll
        for (int off = 16; off; off >>= 1) {
            float ov = __shfl_down_sync(0xffffffffu, bv, off);
            int   oi = __shfl_down_sync(0xffffffffu, bi, off);
            if (ov > bv || (ov == bv && oi < bi)) { bv = ov; bi = oi; }
        }
        if (lane == 0) { wv_[w] = bv; wi_[w] = bi; }
        __syncthreads();
        if (tid == 0) {
            float fb = wv_[0]; int fi = wi_[0];
#pragma unroll
            for (int k = 1; k < 8; k++)
                if (wv_[k] > fb || (wv_[k] == fb && wi_[k] < fi)) { fb = wv_[k]; fi = wi_[k]; }
            selv[r] = fb; seli[r] = fi;
        }
        __syncthreads();
    }
    if (tid == 0) {
        float m = selv[0];
        float e[KTOP]; float sum = 0.f;
#pragma unroll
        for (int r = 0; r < KTOP; r++) { e[r] = expf(selv[r] - m); sum += e[r]; }
#pragma unroll
        for (int r = 0; r < KTOP; r++) {
            g_w[b * KTOP + r] = e[r] / sum;
            g_shift[b * KTOP + r] = seli[r];
        }
    }
}

// K5: transpose both 512x512 weights + tf32 round + K-permute columns.
__global__ void k_transpose512(const float* __restrict__ wv, const float* __restrict__ wo) {
    __shared__ float t[32][33];
    const float* w = blockIdx.z ? wo : wv;
    float* wt = blockIdx.z ? g_woT : g_wvT;
    int x0 = blockIdx.x * 32, y0 = blockIdx.y * 32;
    int tx = threadIdx.x, ty = threadIdx.y;
#pragma unroll
    for (int i = ty; i < 32; i += 8) t[i][tx] = w[(size_t)(y0 + i) * Dn + x0 + tx];
    __syncthreads();
    int pc = y0 + kperm(tx);   // permuted K column
#pragma unroll
    for (int i = ty; i < 32; i += 8) wt[(size_t)(x0 + i) * Dn + pc] = tf32r(t[tx][i]);
}

// K6: weighted roll (4 shifts) + 32x32 transpose, writing rows at the
// PERMUTED output-row index; columns (GEMM2 K dim) written rounded + K-permuted.
__global__ void k_rolltrans() {
    int b = blockIdx.z;
    int ch0 = blockIdx.x * 32, l0 = blockIdx.y * 32;
    __shared__ float t[32][33];
    float wj[KTOP]; int sj[KTOP];
#pragma unroll
    for (int j = 0; j < KTOP; j++) { wj[j] = g_w[b * KTOP + j]; sj[j] = g_shift[b * KTOP + j]; }
    int tx = threadIdx.x, ty = threadIdx.y;   // (32, 8)
#pragma unroll
    for (int q2 = 0; q2 < 4; q2++) {
        int ll = ty + q2 * 8;
        int l = l0 + ll;
        float acc = 0.f;
#pragma unroll
        for (int j = 0; j < KTOP; j++) {
            int lr = (l + sj[j]) & (Ln - 1);
            acc += wj[j] * g_vproj[((size_t)b * Ln + lr) * Dn + ch0 + tx];
        }
        t[ll][tx] = acc;
    }
    __syncthreads();
    int lblk = l0 >> 9, cbase = l0 & 511;
    int pc = cbase + kperm(tx);
#pragma unroll
    for (int q2 = 0; q2 < 4; q2++) {
        int chl = ty + q2 * 8;
        int ch = ch0 + chl;
        int h = ch >> 6, d = ch & 63;
        int rowo = b * Ln + d * 32 + h * 4 + lblk;
        g_abuf[(size_t)rowo * Dn + pc] = tf32r(t[tx][chl]);
    }
}

// ---------------------------------------------------------------------------
// tf32 mma.sync GEMM: C[M,512] = A[M,512] @ Bt[512,512]^T  (Bt K-major rows,
// stored K-permuted within 8-groups). CTA tile 128x256, 512 threads,
// warp grid 2(m) x 8(n), warp tile 64x32 (4x4 m16n8k8 frags). K staged 32
// wide, 3-stage ring. PREP_A: raw A rounded/permuted in-kernel.
// SMEM pitch 40 floats -> float2 fragment loads conflict-free.

constexpr int LDT      = 40;
constexpr int A_ELEMS  = 128 * LDT;             // 5120 floats
constexpr int B_ELEMS  = 256 * LDT;             // 10240 floats
constexpr int STG_EL   = A_ELEMS + B_ELEMS;     // 15360 floats
constexpr int NBUF     = 3;
constexpr int SMEM_GEMM = NBUF * STG_EL * 4;    // 184320 B
constexpr int NSTG     = 16;                    // 512 / 32
constexpr int GT       = 512;                   // GEMM threads

__device__ __forceinline__ void mma_tf32(float* c, const uint32_t* a, const uint32_t* b) {
    asm volatile(
        "mma.sync.aligned.m16n8k8.row.col.f32.tf32.tf32.f32 "
        "{%0,%1,%2,%3}, {%4,%5,%6,%7}, {%8,%9}, {%0,%1,%2,%3};"
        : "+f"(c[0]), "+f"(c[1]), "+f"(c[2]), "+f"(c[3])
        : "r"(a[0]), "r"(a[1]), "r"(a[2]), "r"(a[3]), "r"(b[0]), "r"(b[1]));
}

template<bool PREP_A>
__global__ __launch_bounds__(GT, 1)
void k_mma_gemm(const float* __restrict__ A, const float* __restrict__ Bt,
                float* __restrict__ C) {
    extern __shared__ __align__(16) float smem[];
    int tid = threadIdx.x, wid = tid >> 5, lane = tid & 31;
    int g = lane >> 2, t = lane & 3;
    int m0 = blockIdx.y * 128, n0 = blockIdx.x * 256;
    int wm = wid >> 3, wn = wid & 7;            // 2 x 8 warp grid, tile 64x32

    uint32_t smem_base = (uint32_t)__cvta_generic_to_shared(smem);

    const float* Ab = A + (size_t)m0 * Dn;
    const float* Bb = Bt + (size_t)n0 * Dn;

    // B (and optionally A) via cp.async.  512 threads: A 1024 f4 -> 2/thread,
    // B 2048 f4 -> 4/thread.
    auto issue = [&](int s) {
        int buf = s % NBUF;
        uint32_t abase = smem_base + (uint32_t)(buf * STG_EL) * 4u;
        uint32_t bbase = abase + (uint32_t)A_ELEMS * 4u;
        if (!PREP_A) {
#pragma unroll
            for (int i = 0; i < 2; i++) {
                int idx = tid + i * GT, r = idx >> 3, f4 = idx & 7;
                CP_ASYNC16(abase + (uint32_t)(r * LDT + f4 * 4) * 4u,
                           Ab + (size_t)r * Dn + s * 32 + f4 * 4);
            }
        }
#pragma unroll
        for (int i = 0; i < 4; i++) {
            int idx = tid + i * GT, r = idx >> 3, f4 = idx & 7;
            CP_ASYNC16(bbase + (uint32_t)(r * LDT + f4 * 4) * 4u,
                       Bb + (size_t)r * Dn + s * 32 + f4 * 4);
        }
        CP_COMMIT();
    };

    // Raw-A path: register prefetch + round/permute store (2 f4 per thread)
    float4 va[2];
    auto ldgA = [&](int s) {
#pragma unroll
        for (int i = 0; i < 2; i++) {
            int idx = tid + i * GT, r = idx >> 3, f4 = idx & 7;
            va[i] = *(const float4*)(Ab + (size_t)r * Dn + s * 32 + f4 * 4);
        }
    };
    auto stsA = [&](int s) {
        int buf = s % NBUF;
        float* dst = smem + buf * STG_EL;
#pragma unroll
        for (int i = 0; i < 2; i++) {
            int idx = tid + i * GT, r = idx >> 3, f4 = idx & 7;
            int grp = f4 >> 1, half = f4 & 1;
            float* p = dst + r * LDT + grp * 8 + half;
            p[0] = tf32r(va[i].x);
            p[2] = tf32r(va[i].y);
            p[4] = tf32r(va[i].z);
            p[6] = tf32r(va[i].w);
        }
    };

    float c[4][4][4];
#pragma unroll
    for (int mi = 0; mi < 4; mi++)
#pragma unroll
        for (int nj = 0; nj < 4; nj++)
#pragma unroll
            for (int e = 0; e < 4; e++) c[mi][nj][e] = 0.f;

    if (PREP_A) {
        ldgA(0); stsA(0);
        issue(0); issue(1);
        ldgA(1);
    } else {
        issue(0); issue(1);
    }

    for (int s = 0; s < NSTG; s++) {
        if (s + 2 < NSTG) {
            issue(s + 2);
            asm volatile("cp.async.wait_group 2;");
        } else if (s + 1 < NSTG) {
            asm volatile("cp.async.wait_group 1;");
        } else {
            asm volatile("cp.async.wait_group 0;");
        }
        __syncthreads();   // A(s) + B(s) visible

        if (PREP_A && s + 1 < NSTG) {
            stsA(s + 1);                       // buf (s+1)%3: last consumed at stage s-2
            if (s + 2 < NSTG) ldgA(s + 2);     // latency hidden across full stage
        }

        int buf = s % NBUF;
        const float* Aw = smem + buf * STG_EL + (wm * 64) * LDT;
        const float* Bw = smem + buf * STG_EL + A_ELEMS + (wn * 32) * LDT;
#pragma unroll
        for (int ks = 0; ks < 4; ks++) {
            int kc = ks * 8 + 2 * t;            // permuted layout: (k=t, k=t+4) adjacent
            uint32_t a[4][4], b[4][2];
#pragma unroll
            for (int mi = 0; mi < 4; mi++) {
                float2 v0 = *(const float2*)(Aw + (mi * 16 + g) * LDT + kc);
                float2 v1 = *(const float2*)(Aw + (mi * 16 + g + 8) * LDT + kc);
                a[mi][0] = __float_as_uint(v0.x);
                a[mi][1] = __float_as_uint(v1.x);
                a[mi][2] = __float_as_uint(v0.y);
                a[mi][3] = __float_as_uint(v1.y);
            }
#pragma unroll
            for (int nj = 0; nj < 4; nj++) {
                float2 v = *(const float2*)(Bw + (nj * 8 + g) * LDT + kc);
                b[nj][0] = __float_as_uint(v.x);
                b[nj][1] = __float_as_uint(v.y);
            }
#pragma unroll
            for (int mi = 0; mi < 4; mi++)
#pragma unroll
                for (int nj = 0; nj < 4; nj++)
                    mma_tf32(c[mi][nj], a[mi], b[nj]);
        }
        __syncthreads();
    }

    // epilogue: per-frag float2 stores
#pragma unroll
    for (int mi = 0; mi < 4; mi++) {
        int row = m0 + wm * 64 + mi * 16 + g;
        float* r0 = C + (size_t)row * Dn + n0 + wn * 32 + 2 * t;
        float* r1 = r0 + 8 * Dn;
#pragma unroll
        for (int nj = 0; nj < 4; nj++) {
            *(float2*)(r0 + nj * 8) = make_float2(c[mi][nj][0], c[mi][nj][1]);
            *(float2*)(r1 + nj * 8) = make_float2(c[mi][nj][2], c[mi][nj][3]);
        }
    }
}

// ---------------------------------------------------------------------------
extern "C" void kernel_launch(void* const* d_in, const int* in_sizes, int n_in,
                              void* d_out, int out_size) {
    const float* queries = (const float*)d_in[0];
    const float* keys    = (const float*)d_in[1];
    const float* values  = (const float*)d_in[2];
    const float* wq      = (const float*)d_in[3];
    const float* wk      = (const float*)d_in[4];
    const float* wv      = (const float*)d_in[5];
    const float* wo      = (const float*)d_in[6];
    float* out = (float*)d_out;

    void *vp = nullptr, *ab = nullptr, *wvt = nullptr, *wot = nullptr;
    cudaGetSymbolAddress(&vp,  g_vproj);
    cudaGetSymbolAddress(&ab,  g_abuf);
    cudaGetSymbolAddress(&wvt, g_wvT);
    cudaGetSymbolAddress(&wot, g_woT);

    cudaFuncSetAttribute(k_mma_gemm<true>,  cudaFuncAttributeMaxDynamicSharedMemorySize, SMEM_GEMM);
    cudaFuncSetAttribute(k_mma_gemm<false>, cudaFuncAttributeMaxDynamicSharedMemorySize, SMEM_GEMM);

    // Side streams + events for fork/join under graph capture (host objects only).
    static cudaStream_t sA = nullptr, sB = nullptr;
    static cudaEvent_t ev0 = nullptr, evTop = nullptr, evW = nullptr;
    if (sA == nullptr) {
        cudaStreamCreateWithFlags(&sA, cudaStreamNonBlocking);
        cudaStreamCreateWithFlags(&sB, cudaStreamNonBlocking);
        cudaEventCreateWithFlags(&ev0,   cudaEventDisableTiming);
        cudaEventCreateWithFlags(&evTop, cudaEventDisableTiming);
        cudaEventCreateWithFlags(&evW,   cudaEventDisableTiming);
    }

    // fork
    cudaEventRecord(ev0, 0);
    cudaStreamWaitEvent(sA, ev0, 0);
    cudaStreamWaitEvent(sB, ev0, 0);

    // side stream A: scoring chain (result: g_w, g_shift)
    k_colsum_partial<<<Bn * 16, Dn, 0, sA>>>(queries);
    k_project_u<<<Bn, Dn, 0, sA>>>(wq, wk);
    k_score<<<BLn / 8, 256, 0, sA>>>(keys);
    k_topk<<<Bn, 256, 0, sA>>>();
    cudaEventRecord(evTop, sA);

    // side stream B: weight transposes (result: g_wvT, g_woT)
    k_transpose512<<<dim3(16, 16, 2), dim3(32, 8), 0, sB>>>(wv, wo);
    cudaEventRecord(evW, sB);

    // main stream: GEMM1 (raw A, in-kernel round+permute; needs g_wvT)
    //              -> rolltrans -> GEMM2
    cudaStreamWaitEvent(0, evW, 0);
    k_mma_gemm<true><<<dim3(Dn / 256, BLn / 128), GT, SMEM_GEMM>>>(values, (const float*)wvt, (float*)vp);
    cudaStreamWaitEvent(0, evTop, 0);
    k_rolltrans<<<dim3(Dn / 32, Ln / 32, Bn), dim3(32, 8)>>>();
    k_mma_gemm<false><<<dim3(Dn / 256, BLn / 128), GT, SMEM_GEMM>>>((const float*)ab, (const float*)wot, out);
}

// round 10
// speedup vs baseline: 1.0003x; 1.0003x over previous
#include <cuda_runtime.h>
#include <math.h>
#include <stdint.h>

// Problem constants (fixed shapes)
constexpr int Bn   = 4;
constexpr int Ln   = 2048;
constexpr int Dn   = 512;
constexpr int BLn  = Bn * Ln;   // 8192
constexpr int KTOP = 4;         // int(log(64)) = 4

// Scratch (device globals — no runtime allocation)
__device__ float g_vproj[BLn * Dn];      // values @ wv
__device__ float g_abuf [BLn * Dn];      // permuted weighted-rolled transpose (rounded + K-permuted)
__device__ float g_wvT  [Dn * Dn];       // wv transposed, rounded + K-permuted
__device__ float g_woT  [Dn * Dn];       // wo transposed, rounded + K-permuted
__device__ float g_partial[Bn * 16 * Dn];
__device__ float g_u    [Bn * Dn];
__device__ float g_score[Bn * Ln];
__device__ float g_w    [Bn * KTOP];
__device__ int   g_shift[Bn * KTOP];

// ---------------------------------------------------------------------------
__device__ __forceinline__ float tf32r(float x) {
    uint32_t u;
    asm("cvt.rna.tf32.f32 %0, %1;" : "=r"(u) : "f"(x));
    return __uint_as_float(u);
}
// K-permutation within each 8-group: k<4 -> 2k, k>=4 -> 2(k-4)+1
__device__ __forceinline__ int kperm(int k) {
    int low = k & 7;
    return (k & ~7) | ((low < 4) ? (low << 1) : (((low - 4) << 1) | 1));
}

#define CP_ASYNC16(dst_u32, src_ptr) \
    asm volatile("cp.async.cg.shared.global [%0], [%1], 16;" :: "r"(dst_u32), "l"(src_ptr))
#define CP_COMMIT() asm volatile("cp.async.commit_group;")

// ---------------------------------------------------------------------------
// K1a: partial column sums of queries over 128-row chunks
__global__ void k_colsum_partial(const float* __restrict__ q) {
    int b = blockIdx.x >> 4, lc = blockIdx.x & 15, m = threadIdx.x;
    const float* p = q + ((size_t)(b * Ln + lc * 128)) * Dn + m;
    float acc = 0.f;
#pragma unroll 8
    for (int r = 0; r < 128; r++) acc += p[(size_t)r * Dn];
    g_partial[(size_t)blockIdx.x * Dn + m] = acc;
}

// K2: qmean reduce + qbar = qmean @ wq ; u = wk @ qbar   (one block per batch)
__global__ void k_project_u(const float* __restrict__ wq, const float* __restrict__ wk) {
    int b = blockIdx.x, tid = threadIdx.x;   // 512 threads
    __shared__ float sq[Dn];
    __shared__ float sqb[Dn];
    {
        float acc = 0.f;
#pragma unroll
        for (int lc = 0; lc < 16; lc++) acc += g_partial[(size_t)(b * 16 + lc) * Dn + tid];
        sq[tid] = acc * (1.0f / Ln);
    }
    __syncthreads();
    float acc = 0.f;
    for (int k2 = 0; k2 < Dn; k2++) acc += sq[k2] * wq[(size_t)k2 * Dn + tid];
    sqb[tid] = acc;
    __syncthreads();
    int lane = tid & 31, w = tid >> 5;       // 16 warps
    for (int d = w; d < Dn; d += 16) {
        const float4* row = (const float4*)(wk + (size_t)d * Dn);
        float s = 0.f;
#pragma unroll
        for (int i = 0; i < 4; i++) {
            int idx = lane + i * 32;
            float4 v = row[idx];
            s += v.x * sqb[idx * 4] + v.y * sqb[idx * 4 + 1] +
                 v.z * sqb[idx * 4 + 2] + v.w * sqb[idx * 4 + 3];
        }
        for (int off = 16; off; off >>= 1) s += __shfl_down_sync(0xffffffffu, s, off);
        if (lane == 0) g_u[b * Dn + d] = s;
    }
}

// K3: score[b,j] = (1/8) * <keys[b,j,:], u[b,:]> — one warp per row
__global__ void k_score(const float* __restrict__ keys) {
    int j = blockIdx.x * 8 + (threadIdx.x >> 5);
    int lane = threadIdx.x & 31;
    int b = j >> 11;
    const float4* kr = (const float4*)(keys + (size_t)j * Dn);
    const float4* ur = (const float4*)(g_u + (size_t)b * Dn);
    float s = 0.f;
#pragma unroll
    for (int i = 0; i < 4; i++) {
        float4 kv = kr[lane + i * 32];
        float4 uv = ur[lane + i * 32];
        s += kv.x * uv.x + kv.y * uv.y + kv.z * uv.z + kv.w * uv.w;
    }
    for (int off = 16; off; off >>= 1) s += __shfl_down_sync(0xffffffffu, s, off);
    if (lane == 0) g_score[j] = s * 0.125f;
}

// K4: top-4 (descending, ties -> lower index) + softmax. Register-resident.
__global__ void k_topk() {
    int b = blockIdx.x, tid = threadIdx.x;   // 256 threads, 8 warps
    int lane = tid & 31, w = tid >> 5;
    float v[8]; int vi[8];
#pragma unroll
    for (int i = 0; i < 8; i++) {
        int idx = tid + i * 256;
        v[i] = g_score[b * Ln + idx];
        vi[i] = idx;
    }
    __shared__ float wv_[8];
    __shared__ int   wi_[8];
    __shared__ float selv[KTOP];
    __shared__ int   seli[KTOP];
    if (tid < KTOP) seli[tid] = -1;
    __syncthreads();
    for (int r = 0; r < KTOP; r++) {
        float bv = -3.4e38f; int bi = 0x7fffffff;
#pragma unroll
        for (int i = 0; i < 8; i++) {
            bool dead = false;
#pragma unroll
            for (int p = 0; p < KTOP; p++) dead |= (p < r && vi[i] == seli[p]);
            float x = dead ? -3.4e38f : v[i];
            if (x > bv || (x == bv && vi[i] < bi)) { bv = x; bi = vi[i]; }
        }
#pragma unroll
        for (int off = 16; off; off >>= 1) {
            float ov = __shfl_down_sync(0xffffffffu, bv, off);
            int   oi = __shfl_down_sync(0xffffffffu, bi, off);
            if (ov > bv || (ov == bv && oi < bi)) { bv = ov; bi = oi; }
        }
        if (lane == 0) { wv_[w] = bv; wi_[w] = bi; }
        __syncthreads();
        if (tid == 0) {
            float fb = wv_[0]; int fi = wi_[0];
#pragma unroll
            for (int k = 1; k < 8; k++)
                if (wv_[k] > fb || (wv_[k] == fb && wi_[k] < fi)) { fb = wv_[k]; fi = wi_[k]; }
            selv[r] = fb; seli[r] = fi;
        }
        __syncthreads();
    }
    if (tid == 0) {
        float m = selv[0];
        float e[KTOP]; float sum = 0.f;
#pragma unroll
        for (int r = 0; r < KTOP; r++) { e[r] = expf(selv[r] - m); sum += e[r]; }
#pragma unroll
        for (int r = 0; r < KTOP; r++) {
            g_w[b * KTOP + r] = e[r] / sum;
            g_shift[b * KTOP + r] = seli[r];
        }
    }
}

// K5: transpose both 512x512 weights + tf32 round + K-permute columns.
__global__ void k_transpose512(const float* __restrict__ wv, const float* __restrict__ wo) {
    __shared__ float t[32][33];
    const float* w = blockIdx.z ? wo : wv;
    float* wt = blockIdx.z ? g_woT : g_wvT;
    int x0 = blockIdx.x * 32, y0 = blockIdx.y * 32;
    int tx = threadIdx.x, ty = threadIdx.y;
#pragma unroll
    for (int i = ty; i < 32; i += 8) t[i][tx] = w[(size_t)(y0 + i) * Dn + x0 + tx];
    __syncthreads();
    int pc = y0 + kperm(tx);   // permuted K column
#pragma unroll
    for (int i = ty; i < 32; i += 8) wt[(size_t)(x0 + i) * Dn + pc] = tf32r(t[tx][i]);
}

// K6: weighted roll (4 shifts) + 32x32 transpose, writing rows at the
// PERMUTED output-row index; columns (GEMM2 K dim) written rounded + K-permuted.
__global__ void k_rolltrans() {
    int b = blockIdx.z;
    int ch0 = blockIdx.x * 32, l0 = blockIdx.y * 32;
    __shared__ float t[32][33];
    float wj[KTOP]; int sj[KTOP];
#pragma unroll
    for (int j = 0; j < KTOP; j++) { wj[j] = g_w[b * KTOP + j]; sj[j] = g_shift[b * KTOP + j]; }
    int tx = threadIdx.x, ty = threadIdx.y;   // (32, 8)
#pragma unroll
    for (int q2 = 0; q2 < 4; q2++) {
        int ll = ty + q2 * 8;
        int l = l0 + ll;
        float acc = 0.f;
#pragma unroll
        for (int j = 0; j < KTOP; j++) {
            int lr = (l + sj[j]) & (Ln - 1);
            acc += wj[j] * g_vproj[((size_t)b * Ln + lr) * Dn + ch0 + tx];
        }
        t[ll][tx] = acc;
    }
    __syncthreads();
    int lblk = l0 >> 9, cbase = l0 & 511;
    int pc = cbase + kperm(tx);
#pragma unroll
    for (int q2 = 0; q2 < 4; q2++) {
        int chl = ty + q2 * 8;
        int ch = ch0 + chl;
        int h = ch >> 6, d = ch & 63;
        int rowo = b * Ln + d * 32 + h * 4 + lblk;
        g_abuf[(size_t)rowo * Dn + pc] = tf32r(t[tx][chl]);
    }
}

// ---------------------------------------------------------------------------
// tf32 mma.sync GEMM: C[M,512] = A[M,512] @ Bt[512,512]^T  (Bt K-major rows,
// stored K-permuted within 8-groups). CTA tile 128x256, 512 threads,
// warp grid 2(m) x 8(n), warp tile 64x32 (4x4 m16n8k8 frags). K staged 32
// wide, 3-stage ring. PREP_A: raw A rounded/permuted in-kernel.
// SMEM pitch 40 floats -> float2 fragment loads conflict-free.

constexpr int LDT      = 40;
constexpr int A_ELEMS  = 128 * LDT;             // 5120 floats
constexpr int B_ELEMS  = 256 * LDT;             // 10240 floats
constexpr int STG_EL   = A_ELEMS + B_ELEMS;     // 15360 floats
constexpr int NBUF     = 3;
constexpr int SMEM_GEMM = NBUF * STG_EL * 4;    // 184320 B
constexpr int NSTG     = 16;                    // 512 / 32
constexpr int GT       = 512;                   // GEMM threads

__device__ __forceinline__ void mma_tf32(float* c, const uint32_t* a, const uint32_t* b) {
    asm volatile(
        "mma.sync.aligned.m16n8k8.row.col.f32.tf32.tf32.f32 "
        "{%0,%1,%2,%3}, {%4,%5,%6,%7}, {%8,%9}, {%0,%1,%2,%3};"
        : "+f"(c[0]), "+f"(c[1]), "+f"(c[2]), "+f"(c[3])
        : "r"(a[0]), "r"(a[1]), "r"(a[2]), "r"(a[3]), "r"(b[0]), "r"(b[1]));
}

template<bool PREP_A>
__global__ __launch_bounds__(GT, 1)
void k_mma_gemm(const float* __restrict__ A, const float* __restrict__ Bt,
                float* __restrict__ C) {
    extern __shared__ __align__(16) float smem[];
    int tid = threadIdx.x, wid = tid >> 5, lane = tid & 31;
    int g = lane >> 2, t = lane & 3;
    int m0 = blockIdx.y * 128, n0 = blockIdx.x * 256;
    int wm = wid >> 3, wn = wid & 7;            // 2 x 8 warp grid, tile 64x32

    uint32_t smem_base = (uint32_t)__cvta_generic_to_shared(smem);

    const float* Ab = A + (size_t)m0 * Dn;
    const float* Bb = Bt + (size_t)n0 * Dn;

    // B (and optionally A) via cp.async.  512 threads: A 1024 f4 -> 2/thread,
    // B 2048 f4 -> 4/thread.
    auto issue = [&](int s) {
        int buf = s % NBUF;
        uint32_t abase = smem_base + (uint32_t)(buf * STG_EL) * 4u;
        uint32_t bbase = abase + (uint32_t)A_ELEMS * 4u;
        if (!PREP_A) {
#pragma unroll
            for (int i = 0; i < 2; i++) {
                int idx = tid + i * GT, r = idx >> 3, f4 = idx & 7;
                CP_ASYNC16(abase + (uint32_t)(r * LDT + f4 * 4) * 4u,
                           Ab + (size_t)r * Dn + s * 32 + f4 * 4);
            }
        }
#pragma unroll
        for (int i = 0; i < 4; i++) {
            int idx = tid + i * GT, r = idx >> 3, f4 = idx & 7;
            CP_ASYNC16(bbase + (uint32_t)(r * LDT + f4 * 4) * 4u,
                       Bb + (size_t)r * Dn + s * 32 + f4 * 4);
        }
        CP_COMMIT();
    };

    // Raw-A path: register prefetch + round/permute store (2 f4 per thread)
    float4 va[2];
    auto ldgA = [&](int s) {
#pragma unroll
        for (int i = 0; i < 2; i++) {
            int idx = tid + i * GT, r = idx >> 3, f4 = idx & 7;
            va[i] = *(const float4*)(Ab + (size_t)r * Dn + s * 32 + f4 * 4);
        }
    };
    auto stsA = [&](int s) {
        int buf = s % NBUF;
        float* dst = smem + buf * STG_EL;
#pragma unroll
        for (int i = 0; i < 2; i++) {
            int idx = tid + i * GT, r = idx >> 3, f4 = idx & 7;
            int grp = f4 >> 1, half = f4 & 1;
            float* p = dst + r * LDT + grp * 8 + half;
            p[0] = tf32r(va[i].x);
            p[2] = tf32r(va[i].y);
            p[4] = tf32r(va[i].z);
            p[6] = tf32r(va[i].w);
        }
    };

    float c[4][4][4];
#pragma unroll
    for (int mi = 0; mi < 4; mi++)
#pragma unroll
        for (int nj = 0; nj < 4; nj++)
#pragma unroll
            for (int e = 0; e < 4; e++) c[mi][nj][e] = 0.f;

    if (PREP_A) {
        ldgA(0); stsA(0);
        issue(0); issue(1);
        ldgA(1);
    } else {
        issue(0); issue(1);
    }

    for (int s = 0; s < NSTG; s++) {
        if (s + 2 < NSTG) {
            issue(s + 2);
            asm volatile("cp.async.wait_group 2;");
        } else if (s + 1 < NSTG) {
            asm volatile("cp.async.wait_group 1;");
        } else {
            asm volatile("cp.async.wait_group 0;");
        }
        __syncthreads();   // A(s) + B(s) visible

        if (PREP_A && s + 1 < NSTG) {
            stsA(s + 1);                       // buf (s+1)%3: last consumed at stage s-2
            if (s + 2 < NSTG) ldgA(s + 2);     // latency hidden across full stage
        }

        int buf = s % NBUF;
        const float* Aw = smem + buf * STG_EL + (wm * 64) * LDT;
        const float* Bw = smem + buf * STG_EL + A_ELEMS + (wn * 32) * LDT;
#pragma unroll
        for (int ks = 0; ks < 4; ks++) {
            int kc = ks * 8 + 2 * t;            // permuted layout: (k=t, k=t+4) adjacent
            uint32_t a[4][4], b[4][2];
#pragma unroll
            for (int mi = 0; mi < 4; mi++) {
                float2 v0 = *(const float2*)(Aw + (mi * 16 + g) * LDT + kc);
                float2 v1 = *(const float2*)(Aw + (mi * 16 + g + 8) * LDT + kc);
                a[mi][0] = __float_as_uint(v0.x);
                a[mi][1] = __float_as_uint(v1.x);
                a[mi][2] = __float_as_uint(v0.y);
                a[mi][3] = __float_as_uint(v1.y);
            }
#pragma unroll
            for (int nj = 0; nj < 4; nj++) {
                float2 v = *(const float2*)(Bw + (nj * 8 + g) * LDT + kc);
                b[nj][0] = __float_as_uint(v.x);
                b[nj][1] = __float_as_uint(v.y);
            }
#pragma unroll
            for (int mi = 0; mi < 4; mi++)
#pragma unroll
                for (int nj = 0; nj < 4; nj++)
                    mma_tf32(c[mi][nj], a[mi], b[nj]);
        }
        __syncthreads();
    }

    // epilogue: per-frag float2 stores
#pragma unroll
    for (int mi = 0; mi < 4; mi++) {
        int row = m0 + wm * 64 + mi * 16 + g;
        float* r0 = C + (size_t)row * Dn + n0 + wn * 32 + 2 * t;
        float* r1 = r0 + 8 * Dn;
#pragma unroll
        for (int nj = 0; nj < 4; nj++) {
            *(float2*)(r0 + nj * 8) = make_float2(c[mi][nj][0], c[mi][nj][1]);
            *(float2*)(r1 + nj * 8) = make_float2(c[mi][nj][2], c[mi][nj][3]);
        }
    }
}

// ---------------------------------------------------------------------------
extern "C" void kernel_launch(void* const* d_in, const int* in_sizes, int n_in,
                              void* d_out, int out_size) {
    const float* queries = (const float*)d_in[0];
    const float* keys    = (const float*)d_in[1];
    const float* values  = (const float*)d_in[2];
    const float* wq      = (const float*)d_in[3];
    const float* wk      = (const float*)d_in[4];
    const float* wv      = (const float*)d_in[5];
    const float* wo      = (const float*)d_in[6];
    float* out = (float*)d_out;

    void *vp = nullptr, *ab = nullptr, *wvt = nullptr, *wot = nullptr;
    cudaGetSymbolAddress(&vp,  g_vproj);
    cudaGetSymbolAddress(&ab,  g_abuf);
    cudaGetSymbolAddress(&wvt, g_wvT);
    cudaGetSymbolAddress(&wot, g_woT);

    cudaFuncSetAttribute(k_mma_gemm<true>,  cudaFuncAttributeMaxDynamicSharedMemorySize, SMEM_GEMM);
    cudaFuncSetAttribute(k_mma_gemm<false>, cudaFuncAttributeMaxDynamicSharedMemorySize, SMEM_GEMM);

    // Side streams + events for fork/join under graph capture (host objects only).
    static cudaStream_t sA = nullptr, sB = nullptr;
    static cudaEvent_t ev0 = nullptr, evTop = nullptr, evW = nullptr;
    if (sA == nullptr) {
        cudaStreamCreateWithFlags(&sA, cudaStreamNonBlocking);
        cudaStreamCreateWithFlags(&sB, cudaStreamNonBlocking);
        cudaEventCreateWithFlags(&ev0,   cudaEventDisableTiming);
        cudaEventCreateWithFlags(&evTop, cudaEventDisableTiming);
        cudaEventCreateWithFlags(&evW,   cudaEventDisableTiming);
    }

    // fork
    cudaEventRecord(ev0, 0);
    cudaStreamWaitEvent(sA, ev0, 0);
    cudaStreamWaitEvent(sB, ev0, 0);

    // side stream A: scoring chain (result: g_w, g_shift)
    k_colsum_partial<<<Bn * 16, Dn, 0, sA>>>(queries);
    k_project_u<<<Bn, Dn, 0, sA>>>(wq, wk);
    k_score<<<BLn / 8, 256, 0, sA>>>(keys);
    k_topk<<<Bn, 256, 0, sA>>>();
    cudaEventRecord(evTop, sA);

    // side stream B: weight transposes (result: g_wvT, g_woT)
    k_transpose512<<<dim3(16, 16, 2), dim3(32, 8), 0, sB>>>(wv, wo);
    cudaEventRecord(evW, sB);

    // main stream: GEMM1 (raw A, in-kernel round+permute; needs g_wvT)
    //              -> rolltrans -> GEMM2
    cudaStreamWaitEvent(0, evW, 0);
    k_mma_gemm<true><<<dim3(Dn / 256, BLn / 128), GT, SMEM_GEMM>>>(values, (const float*)wvt, (float*)vp);
    cudaStreamWaitEvent(0, evTop, 0);
    k_rolltrans<<<dim3(Dn / 32, Ln / 32, Bn), dim3(32, 8)>>>();
    k_mma_gemm<false><<<dim3(Dn / 256, BLn / 128), GT, SMEM_GEMM>>>((const float*)ab, (const float*)wot, out);
}

// round 11
// speedup vs baseline: 1.0010x; 1.0008x over previous
#include <cuda_runtime.h>
#include <math.h>
#include <stdint.h>

// Problem constants (fixed shapes)
constexpr int Bn   = 4;
constexpr int Ln   = 2048;
constexpr int Dn   = 512;
constexpr int BLn  = Bn * Ln;   // 8192
constexpr int KTOP = 4;         // int(log(64)) = 4

// Scratch (device globals — no runtime allocation)
__device__ float g_vproj[BLn * Dn];      // values @ wv
__device__ float g_abuf [BLn * Dn];      // permuted weighted-rolled transpose (rounded + K-permuted)
__device__ float g_wvT  [Dn * Dn];       // wv transposed, rounded + K-permuted
__device__ float g_woT  [Dn * Dn];       // wo transposed, rounded + K-permuted
__device__ float g_partial[Bn * 16 * Dn];
__device__ float g_u    [Bn * Dn];
__device__ float g_score[Bn * Ln];
__device__ float g_w    [Bn * KTOP];
__device__ int   g_shift[Bn * KTOP];

// ---------------------------------------------------------------------------
__device__ __forceinline__ float tf32r(float x) {
    uint32_t u;
    asm("cvt.rna.tf32.f32 %0, %1;" : "=r"(u) : "f"(x));
    return __uint_as_float(u);
}
// K-permutation within each 8-group: k<4 -> 2k, k>=4 -> 2(k-4)+1
__device__ __forceinline__ int kperm(int k) {
    int low = k & 7;
    return (k & ~7) | ((low < 4) ? (low << 1) : (((low - 4) << 1) | 1));
}

#define CP_ASYNC16(dst_u32, src_ptr) \
    asm volatile("cp.async.cg.shared.global [%0], [%1], 16;" :: "r"(dst_u32), "l"(src_ptr))
#define CP_COMMIT() asm volatile("cp.async.commit_group;")

// ---------------------------------------------------------------------------
// K1a: partial column sums of queries over 128-row chunks
__global__ void k_colsum_partial(const float* __restrict__ q) {
    int b = blockIdx.x >> 4, lc = blockIdx.x & 15, m = threadIdx.x;
    const float* p = q + ((size_t)(b * Ln + lc * 128)) * Dn + m;
    float acc = 0.f;
#pragma unroll 8
    for (int r = 0; r < 128; r++) acc += p[(size_t)r * Dn];
    g_partial[(size_t)blockIdx.x * Dn + m] = acc;
}

// K2: qmean reduce + qbar = qmean @ wq ; u = wk @ qbar   (one block per batch)
__global__ void k_project_u(const float* __restrict__ wq, const float* __restrict__ wk) {
    int b = blockIdx.x, tid = threadIdx.x;   // 512 threads
    __shared__ float sq[Dn];
    __shared__ float sqb[Dn];
    {
        float acc = 0.f;
#pragma unroll
        for (int lc = 0; lc < 16; lc++) acc += g_partial[(size_t)(b * 16 + lc) * Dn + tid];
        sq[tid] = acc * (1.0f / Ln);
    }
    __syncthreads();
    float acc = 0.f;
    for (int k2 = 0; k2 < Dn; k2++) acc += sq[k2] * wq[(size_t)k2 * Dn + tid];
    sqb[tid] = acc;
    __syncthreads();
    int lane = tid & 31, w = tid >> 5;       // 16 warps
    for (int d = w; d < Dn; d += 16) {
        const float4* row = (const float4*)(wk + (size_t)d * Dn);
        float s = 0.f;
#pragma unroll
        for (int i = 0; i < 4; i++) {
            int idx = lane + i * 32;
            float4 v = row[idx];
            s += v.x * sqb[idx * 4] + v.y * sqb[idx * 4 + 1] +
                 v.z * sqb[idx * 4 + 2] + v.w * sqb[idx * 4 + 3];
        }
        for (int off = 16; off; off >>= 1) s += __shfl_down_sync(0xffffffffu, s, off);
        if (lane == 0) g_u[b * Dn + d] = s;
    }
}

// K3: score[b,j] = (1/8) * <keys[b,j,:], u[b,:]> — one warp per row
__global__ void k_score(const float* __restrict__ keys) {
    int j = blockIdx.x * 8 + (threadIdx.x >> 5);
    int lane = threadIdx.x & 31;
    int b = j >> 11;
    const float4* kr = (const float4*)(keys + (size_t)j * Dn);
    const float4* ur = (const float4*)(g_u + (size_t)b * Dn);
    float s = 0.f;
#pragma unroll
    for (int i = 0; i < 4; i++) {
        float4 kv = kr[lane + i * 32];
        float4 uv = ur[lane + i * 32];
        s += kv.x * uv.x + kv.y * uv.y + kv.z * uv.z + kv.w * uv.w;
    }
    for (int off = 16; off; off >>= 1) s += __shfl_down_sync(0xffffffffu, s, off);
    if (lane == 0) g_score[j] = s * 0.125f;
}

// K4: top-4 (descending, ties -> lower index) + softmax. Register-resident.
__global__ void k_topk() {
    int b = blockIdx.x, tid = threadIdx.x;   // 256 threads, 8 warps
    int lane = tid & 31, w = tid >> 5;
    float v[8]; int vi[8];
#pragma unroll
    for (int i = 0; i < 8; i++) {
        int idx = tid + i * 256;
        v[i] = g_score[b * Ln + idx];
        vi[i] = idx;
    }
    __shared__ float wv_[8];
    __shared__ int   wi_[8];
    __shared__ float selv[KTOP];
    __shared__ int   seli[KTOP];
    if (tid < KTOP) seli[tid] = -1;
    __syncthreads();
    for (int r = 0; r < KTOP; r++) {
        float bv = -3.4e38f; int bi = 0x7fffffff;
#pragma unroll
        for (int i = 0; i < 8; i++) {
            bool dead = false;
#pragma unroll
            for (int p = 0; p < KTOP; p++) dead |= (p < r && vi[i] == seli[p]);
            float x = dead ? -3.4e38f : v[i];
            if (x > bv || (x == bv && vi[i] < bi)) { bv = x; bi = vi[i]; }
        }
#pragma unroll
        for (int off = 16; off; off >>= 1) {
            float ov = __shfl_down_sync(0xffffffffu, bv, off);
            int   oi = __shfl_down_sync(0xffffffffu, bi, off);
            if (ov > bv || (ov == bv && oi < bi)) { bv = ov; bi = oi; }
        }
        if (lane == 0) { wv_[w] = bv; wi_[w] = bi; }
        __syncthreads();
        if (tid == 0) {
            float fb = wv_[0]; int fi = wi_[0];
#pragma unroll
            for (int k = 1; k < 8; k++)
                if (wv_[k] > fb || (wv_[k] == fb && wi_[k] < fi)) { fb = wv_[k]; fi = wi_[k]; }
            selv[r] = fb; seli[r] = fi;
        }
        __syncthreads();
    }
    if (tid == 0) {
        float m = selv[0];
        float e[KTOP]; float sum = 0.f;
#pragma unroll
        for (int r = 0; r < KTOP; r++) { e[r] = expf(selv[r] - m); sum += e[r]; }
#pragma unroll
        for (int r = 0; r < KTOP; r++) {
            g_w[b * KTOP + r] = e[r] / sum;
            g_shift[b * KTOP + r] = seli[r];
        }
    }
}

// K5: transpose both 512x512 weights + tf32 round + K-permute columns.
__global__ void k_transpose512(const float* __restrict__ wv, const float* __restrict__ wo) {
    __shared__ float t[32][33];
    const float* w = blockIdx.z ? wo : wv;
    float* wt = blockIdx.z ? g_woT : g_wvT;
    int x0 = blockIdx.x * 32, y0 = blockIdx.y * 32;
    int tx = threadIdx.x, ty = threadIdx.y;
#pragma unroll
    for (int i = ty; i < 32; i += 8) t[i][tx] = w[(size_t)(y0 + i) * Dn + x0 + tx];
    __syncthreads();
    int pc = y0 + kperm(tx);   // permuted K column
#pragma unroll
    for (int i = ty; i < 32; i += 8) wt[(size_t)(x0 + i) * Dn + pc] = tf32r(t[tx][i]);
}

// K6: weighted roll (4 shifts) + 32x32 transpose, writing rows at the
// PERMUTED output-row index; columns (GEMM2 K dim) written rounded + K-permuted.
__global__ void k_rolltrans() {
    int b = blockIdx.z;
    int ch0 = blockIdx.x * 32, l0 = blockIdx.y * 32;
    __shared__ float t[32][33];
    float wj[KTOP]; int sj[KTOP];
#pragma unroll
    for (int j = 0; j < KTOP; j++) { wj[j] = g_w[b * KTOP + j]; sj[j] = g_shift[b * KTOP + j]; }
    int tx = threadIdx.x, ty = threadIdx.y;   // (32, 8)
#pragma unroll
    for (int q2 = 0; q2 < 4; q2++) {
        int ll = ty + q2 * 8;
        int l = l0 + ll;
        float acc = 0.f;
#pragma unroll
        for (int j = 0; j < KTOP; j++) {
            int lr = (l + sj[j]) & (Ln - 1);
            acc += wj[j] * g_vproj[((size_t)b * Ln + lr) * Dn + ch0 + tx];
        }
        t[ll][tx] = acc;
    }
    __syncthreads();
    int lblk = l0 >> 9, cbase = l0 & 511;
    int pc = cbase + kperm(tx);
#pragma unroll
    for (int q2 = 0; q2 < 4; q2++) {
        int chl = ty + q2 * 8;
        int ch = ch0 + chl;
        int h = ch >> 6, d = ch & 63;
        int rowo = b * Ln + d * 32 + h * 4 + lblk;
        g_abuf[(size_t)rowo * Dn + pc] = tf32r(t[tx][chl]);
    }
}

// ---------------------------------------------------------------------------
// tf32 mma.sync GEMM: C[M,512] = A[M,512] @ Bt[512,512]^T  (Bt K-major rows,
// stored K-permuted within 8-groups). CTA tile 128x256, 512 threads,
// warp grid 2(m) x 8(n), warp tile 64x32 (4x4 m16n8k8 frags). K staged 32
// wide, 3-stage ring. PREP_A: raw A rounded/permuted in-kernel.
// SMEM pitch 40 floats -> float2 fragment loads conflict-free.

constexpr int LDT      = 40;
constexpr int A_ELEMS  = 128 * LDT;             // 5120 floats
constexpr int B_ELEMS  = 256 * LDT;             // 10240 floats
constexpr int STG_EL   = A_ELEMS + B_ELEMS;     // 15360 floats
constexpr int NBUF     = 3;
constexpr int SMEM_GEMM = NBUF * STG_EL * 4;    // 184320 B
constexpr int NSTG     = 16;                    // 512 / 32
constexpr int GT       = 512;                   // GEMM threads

__device__ __forceinline__ void mma_tf32(float* c, const uint32_t* a, const uint32_t* b) {
    asm volatile(
        "mma.sync.aligned.m16n8k8.row.col.f32.tf32.tf32.f32 "
        "{%0,%1,%2,%3}, {%4,%5,%6,%7}, {%8,%9}, {%0,%1,%2,%3};"
        : "+f"(c[0]), "+f"(c[1]), "+f"(c[2]), "+f"(c[3])
        : "r"(a[0]), "r"(a[1]), "r"(a[2]), "r"(a[3]), "r"(b[0]), "r"(b[1]));
}

template<bool PREP_A>
__global__ __launch_bounds__(GT, 1)
void k_mma_gemm(const float* __restrict__ A, const float* __restrict__ Bt,
                float* __restrict__ C) {
    extern __shared__ __align__(16) float smem[];
    int tid = threadIdx.x, wid = tid >> 5, lane = tid & 31;
    int g = lane >> 2, t = lane & 3;
    int m0 = blockIdx.y * 128, n0 = blockIdx.x * 256;
    int wm = wid >> 3, wn = wid & 7;            // 2 x 8 warp grid, tile 64x32

    uint32_t smem_base = (uint32_t)__cvta_generic_to_shared(smem);

    const float* Ab = A + (size_t)m0 * Dn;
    const float* Bb = Bt + (size_t)n0 * Dn;

    // B (and optionally A) via cp.async.  512 threads: A 1024 f4 -> 2/thread,
    // B 2048 f4 -> 4/thread.
    auto issue = [&](int s) {
        int buf = s % NBUF;
        uint32_t abase = smem_base + (uint32_t)(buf * STG_EL) * 4u;
        uint32_t bbase = abase + (uint32_t)A_ELEMS * 4u;
        if (!PREP_A) {
#pragma unroll
            for (int i = 0; i < 2; i++) {
                int idx = tid + i * GT, r = idx >> 3, f4 = idx & 7;
                CP_ASYNC16(abase + (uint32_t)(r * LDT + f4 * 4) * 4u,
                           Ab + (size_t)r * Dn + s * 32 + f4 * 4);
            }
        }
#pragma unroll
        for (int i = 0; i < 4; i++) {
            int idx = tid + i * GT, r = idx >> 3, f4 = idx & 7;
            CP_ASYNC16(bbase + (uint32_t)(r * LDT + f4 * 4) * 4u,
                       Bb + (size_t)r * Dn + s * 32 + f4 * 4);
        }
        CP_COMMIT();
    };

    // Raw-A path: register prefetch + round/permute store (2 f4 per thread)
    float4 va[2];
    auto ldgA = [&](int s) {
#pragma unroll
        for (int i = 0; i < 2; i++) {
            int idx = tid + i * GT, r = idx >> 3, f4 = idx & 7;
            va[i] = *(const float4*)(Ab + (size_t)r * Dn + s * 32 + f4 * 4);
        }
    };
    auto stsA = [&](int s) {
        int buf = s % NBUF;
        float* dst = smem + buf * STG_EL;
#pragma unroll
        for (int i = 0; i < 2; i++) {
            int idx = tid + i * GT, r = idx >> 3, f4 = idx & 7;
            int grp = f4 >> 1, half = f4 & 1;
            float* p = dst + r * LDT + grp * 8 + half;
            p[0] = tf32r(va[i].x);
            p[2] = tf32r(va[i].y);
            p[4] = tf32r(va[i].z);
            p[6] = tf32r(va[i].w);
        }
    };

    float c[4][4][4];
#pragma unroll
    for (int mi = 0; mi < 4; mi++)
#pragma unroll
        for (int nj = 0; nj < 4; nj++)
#pragma unroll
            for (int e = 0; e < 4; e++) c[mi][nj][e] = 0.f;

    if (PREP_A) {
        ldgA(0); stsA(0);
        issue(0); issue(1);
        ldgA(1);
    } else {
        issue(0); issue(1);
    }

    for (int s = 0; s < NSTG; s++) {
        if (s + 2 < NSTG) {
            issue(s + 2);
            asm volatile("cp.async.wait_group 2;");
        } else if (s + 1 < NSTG) {
            asm volatile("cp.async.wait_group 1;");
        } else {
            asm volatile("cp.async.wait_group 0;");
        }
        __syncthreads();   // A(s) + B(s) visible

        if (PREP_A && s + 1 < NSTG) {
            stsA(s + 1);                       // buf (s+1)%3: last consumed at stage s-2
            if (s + 2 < NSTG) ldgA(s + 2);     // latency hidden across full stage
        }

        int buf = s % NBUF;
        const float* Aw = smem + buf * STG_EL + (wm * 64) * LDT;
        const float* Bw = smem + buf * STG_EL + A_ELEMS + (wn * 32) * LDT;
#pragma unroll
        for (int ks = 0; ks < 4; ks++) {
            int kc = ks * 8 + 2 * t;            // permuted layout: (k=t, k=t+4) adjacent
            uint32_t a[4][4], b[4][2];
#pragma unroll
            for (int mi = 0; mi < 4; mi++) {
                float2 v0 = *(const float2*)(Aw + (mi * 16 + g) * LDT + kc);
                float2 v1 = *(const float2*)(Aw + (mi * 16 + g + 8) * LDT + kc);
                a[mi][0] = __float_as_uint(v0.x);
                a[mi][1] = __float_as_uint(v1.x);
                a[mi][2] = __float_as_uint(v0.y);
                a[mi][3] = __float_as_uint(v1.y);
            }
#pragma unroll
            for (int nj = 0; nj < 4; nj++) {
                float2 v = *(const float2*)(Bw + (nj * 8 + g) * LDT + kc);
                b[nj][0] = __float_as_uint(v.x);
                b[nj][1] = __float_as_uint(v.y);
            }
#pragma unroll
            for (int mi = 0; mi < 4; mi++)
#pragma unroll
                for (int nj = 0; nj < 4; nj++)
                    mma_tf32(c[mi][nj], a[mi], b[nj]);
        }
        __syncthreads();
    }

    // epilogue: per-frag float2 stores
#pragma unroll
    for (int mi = 0; mi < 4; mi++) {
        int row = m0 + wm * 64 + mi * 16 + g;
        float* r0 = C + (size_t)row * Dn + n0 + wn * 32 + 2 * t;
        float* r1 = r0 + 8 * Dn;
#pragma unroll
        for (int nj = 0; nj < 4; nj++) {
            *(float2*)(r0 + nj * 8) = make_float2(c[mi][nj][0], c[mi][nj][1]);
            *(float2*)(r1 + nj * 8) = make_float2(c[mi][nj][2], c[mi][nj][3]);
        }
    }
}

// ---------------------------------------------------------------------------
extern "C" void kernel_launch(void* const* d_in, const int* in_sizes, int n_in,
                              void* d_out, int out_size) {
    const float* queries = (const float*)d_in[0];
    const float* keys    = (const float*)d_in[1];
    const float* values  = (const float*)d_in[2];
    const float* wq      = (const float*)d_in[3];
    const float* wk      = (const float*)d_in[4];
    const float* wv      = (const float*)d_in[5];
    const float* wo      = (const float*)d_in[6];
    float* out = (float*)d_out;

    void *vp = nullptr, *ab = nullptr, *wvt = nullptr, *wot = nullptr;
    cudaGetSymbolAddress(&vp,  g_vproj);
    cudaGetSymbolAddress(&ab,  g_abuf);
    cudaGetSymbolAddress(&wvt, g_wvT);
    cudaGetSymbolAddress(&wot, g_woT);

    cudaFuncSetAttribute(k_mma_gemm<true>,  cudaFuncAttributeMaxDynamicSharedMemorySize, SMEM_GEMM);
    cudaFuncSetAttribute(k_mma_gemm<false>, cudaFuncAttributeMaxDynamicSharedMemorySize, SMEM_GEMM);

    // Side streams + events for fork/join under graph capture (host objects only).
    static cudaStream_t sA = nullptr, sB = nullptr;
    static cudaEvent_t ev0 = nullptr, evTop = nullptr, evW = nullptr;
    if (sA == nullptr) {
        cudaStreamCreateWithFlags(&sA, cudaStreamNonBlocking);
        cudaStreamCreateWithFlags(&sB, cudaStreamNonBlocking);
        cudaEventCreateWithFlags(&ev0,   cudaEventDisableTiming);
        cudaEventCreateWithFlags(&evTop, cudaEventDisableTiming);
        cudaEventCreateWithFlags(&evW,   cudaEventDisableTiming);
    }

    // fork
    cudaEventRecord(ev0, 0);
    cudaStreamWaitEvent(sA, ev0, 0);
    cudaStreamWaitEvent(sB, ev0, 0);

    // side stream A: scoring chain (result: g_w, g_shift)
    k_colsum_partial<<<Bn * 16, Dn, 0, sA>>>(queries);
    k_project_u<<<Bn, Dn, 0, sA>>>(wq, wk);
    k_score<<<BLn / 8, 256, 0, sA>>>(keys);
    k_topk<<<Bn, 256, 0, sA>>>();
    cudaEventRecord(evTop, sA);

    // side stream B: weight transposes (result: g_wvT, g_woT)
    k_transpose512<<<dim3(16, 16, 2), dim3(32, 8), 0, sB>>>(wv, wo);
    cudaEventRecord(evW, sB);

    // main stream: GEMM1 (raw A, in-kernel round+permute; needs g_wvT)
    //              -> rolltrans -> GEMM2
    cudaStreamWaitEvent(0, evW, 0);
    k_mma_gemm<true><<<dim3(Dn / 256, BLn / 128), GT, SMEM_GEMM>>>(values, (const float*)wvt, (float*)vp);
    cudaStreamWaitEvent(0, evTop, 0);
    k_rolltrans<<<dim3(Dn / 32, Ln / 32, Bn), dim3(32, 8)>>>();
    k_mma_gemm<false><<<dim3(Dn / 256, BLn / 128), GT, SMEM_GEMM>>>((const float*)ab, (const float*)wot, out);
}